// round 1
// baseline (speedup 1.0000x reference)
#include <cuda_runtime.h>

#define N_NODES 100000
#define N_EDGES 1600000
#define NB_SCAN 98              // ceil((N_NODES+1)/1024)
#define NEG_SLOPE 0.2f

// ---------------- scratch (device globals; no allocation allowed) ----------------
__device__ int   g_deg[N_NODES + 1];
__device__ int   g_rowptr[N_NODES + 1];
__device__ int   g_cursor[N_NODES];
__device__ int   g_bsum[128];
__device__ int   g_adj[N_EDGES];
__device__ float g_h[N_NODES * 64];      // current layer transformed features
__device__ float g_feat[N_NODES * 64];   // aggregated layer output (input to next)
__device__ float g_as[N_NODES];
__device__ float g_ad[N_NODES];

// ---------------- init: zero degree histogram + output ----------------
__global__ void k_init(float* __restrict__ out) {
    int i = blockIdx.x * blockDim.x + threadIdx.x;
    if (i <= N_NODES) g_deg[i] = 0;
    if (i < 64) out[i] = 0.0f;
}

// ---------------- degree histogram over dst ----------------
__global__ void k_hist(const int* __restrict__ ei) {
    int e = blockIdx.x * blockDim.x + threadIdx.x;
    if (e < N_EDGES) atomicAdd(&g_deg[ei[N_EDGES + e] + 1], 1);
}

// ---------------- 3-kernel inclusive scan of g_deg -> g_rowptr ----------------
__global__ void k_scan1() {
    __shared__ int s[1024];
    int t = threadIdx.x;
    int i = blockIdx.x * 1024 + t;
    int v = (i <= N_NODES) ? g_deg[i] : 0;
    s[t] = v;
    __syncthreads();
    for (int off = 1; off < 1024; off <<= 1) {
        int x = (t >= off) ? s[t - off] : 0;
        __syncthreads();
        s[t] += x;
        __syncthreads();
    }
    if (i <= N_NODES) g_rowptr[i] = s[t];
    if (t == 1023) g_bsum[blockIdx.x] = s[1023];
}

__global__ void k_scan2() {
    if (threadIdx.x == 0) {
        int run = 0;
        for (int b = 0; b < NB_SCAN; b++) { int t = g_bsum[b]; g_bsum[b] = run; run += t; }
    }
}

__global__ void k_scan3() {
    int i = blockIdx.x * 1024 + threadIdx.x;
    if (i <= N_NODES) {
        int v = g_rowptr[i] + g_bsum[blockIdx.x];
        g_rowptr[i] = v;
        if (i < N_NODES) g_cursor[i] = v;
    }
}

// ---------------- fill adjacency (src indices grouped by dst) ----------------
__global__ void k_fill(const int* __restrict__ ei) {
    int e = blockIdx.x * blockDim.x + threadIdx.x;
    if (e < N_EDGES) {
        int d = ei[N_EDGES + e];
        int pos = atomicAdd(&g_cursor[d], 1);
        g_adj[pos] = ei[e];
    }
}

// ---------------- fused GEMM (h = X @ W^T) + attention logits ----------------
// Block = 256 threads = 32 nodes. Thread (nl = tid>>4, og = tid&15) computes
// outputs [og*4, og*4+4) for nodes n0 = base+nl and n1 = n0+16.
// 16 lanes of a half-warp share the node pair -> x loads broadcast in L1.
template <int IN>
__global__ void k_gemm(const float* __restrict__ Xext,
                       const float* __restrict__ W,
                       const float* __restrict__ avsrc,
                       const float* __restrict__ avdst) {
    const float* X = (IN == 128) ? Xext : (const float*)g_feat;
    const int tid = threadIdx.x;
    const int og  = tid & 15;
    const int nl  = tid >> 4;
    const int n0  = blockIdx.x * 32 + nl;
    const int n1  = n0 + 16;
    const int C   = IN / 4;

    const float4* x0 = (const float4*)X + n0 * C;
    const float4* x1 = (const float4*)X + n1 * C;
    const float4* w  = (const float4*)W + (og * 4) * C;

    float a00 = 0.f, a01 = 0.f, a02 = 0.f, a03 = 0.f;
    float a10 = 0.f, a11 = 0.f, a12 = 0.f, a13 = 0.f;

#pragma unroll 4
    for (int c = 0; c < C; c++) {
        float4 xv0 = __ldg(x0 + c);
        float4 xv1 = __ldg(x1 + c);
        float4 w0 = __ldg(w + c);
        float4 w1 = __ldg(w + C + c);
        float4 w2 = __ldg(w + 2 * C + c);
        float4 w3 = __ldg(w + 3 * C + c);
        a00 += xv0.x * w0.x + xv0.y * w0.y + xv0.z * w0.z + xv0.w * w0.w;
        a01 += xv0.x * w1.x + xv0.y * w1.y + xv0.z * w1.z + xv0.w * w1.w;
        a02 += xv0.x * w2.x + xv0.y * w2.y + xv0.z * w2.z + xv0.w * w2.w;
        a03 += xv0.x * w3.x + xv0.y * w3.y + xv0.z * w3.z + xv0.w * w3.w;
        a10 += xv1.x * w0.x + xv1.y * w0.y + xv1.z * w0.z + xv1.w * w0.w;
        a11 += xv1.x * w1.x + xv1.y * w1.y + xv1.z * w1.z + xv1.w * w1.w;
        a12 += xv1.x * w2.x + xv1.y * w2.y + xv1.z * w2.z + xv1.w * w2.w;
        a13 += xv1.x * w3.x + xv1.y * w3.y + xv1.z * w3.z + xv1.w * w3.w;
    }

    float4* H4 = (float4*)g_h;
    H4[n0 * 16 + og] = make_float4(a00, a01, a02, a03);
    H4[n1 * 16 + og] = make_float4(a10, a11, a12, a13);

    // attention logit partials: as = h . a_src, ad = h . a_dst
    float s0 = __ldg(&avsrc[og * 4 + 0]);
    float s1 = __ldg(&avsrc[og * 4 + 1]);
    float s2 = __ldg(&avsrc[og * 4 + 2]);
    float s3 = __ldg(&avsrc[og * 4 + 3]);
    float d0 = __ldg(&avdst[og * 4 + 0]);
    float d1 = __ldg(&avdst[og * 4 + 1]);
    float d2 = __ldg(&avdst[og * 4 + 2]);
    float d3 = __ldg(&avdst[og * 4 + 3]);

    float as0p = a00 * s0 + a01 * s1 + a02 * s2 + a03 * s3;
    float ad0p = a00 * d0 + a01 * d1 + a02 * d2 + a03 * d3;
    float as1p = a10 * s0 + a11 * s1 + a12 * s2 + a13 * s3;
    float ad1p = a10 * d0 + a11 * d1 + a12 * d2 + a13 * d3;

#pragma unroll
    for (int m = 8; m; m >>= 1) {
        as0p += __shfl_xor_sync(0xffffffffu, as0p, m);
        ad0p += __shfl_xor_sync(0xffffffffu, ad0p, m);
        as1p += __shfl_xor_sync(0xffffffffu, as1p, m);
        ad1p += __shfl_xor_sync(0xffffffffu, ad1p, m);
    }
    if (og == 0) {
        g_as[n0] = as0p;
        g_ad[n0] = ad0p;
        g_as[n1] = as1p;
        g_ad[n1] = ad1p;
    }
}

// ---------------- warp-per-node softmax aggregation (atomic-free) ----------------
// exp-max subtraction omitted: logits are O(10), exp cannot overflow in fp32
// and the normalized ratio is mathematically unchanged.
__global__ void k_agg(const float* __restrict__ b, int relu) {
    int gw = (blockIdx.x * blockDim.x + threadIdx.x) >> 5;
    int lane = threadIdx.x & 31;
    if (gw >= N_NODES) return;
    const int node = gw;

    float adn = g_ad[node];
    float e0 = g_as[node] + adn;
    e0 = (e0 > 0.f) ? e0 : NEG_SLOPE * e0;
    float exs = __expf(e0);                       // self-loop term

    float acc0 = exs * g_h[node * 64 + lane];
    float acc1 = exs * g_h[node * 64 + 32 + lane];
    float dsum = 0.f;

    int beg = g_rowptr[node];
    int end = g_rowptr[node + 1];
    for (int k = beg; k < end; k += 32) {
        int idx = k + lane;
        int s = 0;
        float ex = 0.f;
        if (idx < end) {
            s = g_adj[idx];
            float e = g_as[s] + adn;
            e = (e > 0.f) ? e : NEG_SLOPE * e;
            ex = __expf(e);
        }
        dsum += ex;
        int cnt = min(32, end - k);
        for (int j = 0; j < cnt; j++) {
            float exj = __shfl_sync(0xffffffffu, ex, j);
            int sj = __shfl_sync(0xffffffffu, s, j);
            acc0 += exj * g_h[sj * 64 + lane];
            acc1 += exj * g_h[sj * 64 + 32 + lane];
        }
    }
#pragma unroll
    for (int m = 16; m; m >>= 1) dsum += __shfl_xor_sync(0xffffffffu, dsum, m);

    float inv = 1.0f / (dsum + exs);
    float r0 = acc0 * inv + b[lane];
    float r1 = acc1 * inv + b[lane + 32];
    if (relu) { r0 = fmaxf(r0, 0.f); r1 = fmaxf(r1, 0.f); }
    g_feat[node * 64 + lane] = r0;
    g_feat[node * 64 + 32 + lane] = r1;
}

// ---------------- global mean pool ----------------
__global__ void k_mean(float* __restrict__ out) {
    __shared__ float s[64];
    int tid = threadIdx.x;
    if (tid < 64) s[tid] = 0.f;
    __syncthreads();
    float acc = 0.f;
    // stride is a multiple of 64 -> each thread stays on one feature dim
    for (long i = blockIdx.x * blockDim.x + tid; i < (long)N_NODES * 64;
         i += (long)gridDim.x * blockDim.x)
        acc += g_feat[i];
    atomicAdd(&s[tid & 63], acc);
    __syncthreads();
    if (tid < 64) atomicAdd(&out[tid], s[tid] * (1.0f / N_NODES));
}

// ---------------- launch ----------------
extern "C" void kernel_launch(void* const* d_in, const int* in_sizes, int n_in,
                              void* d_out, int out_size) {
    const float* x   = (const float*)d_in[0];
    const int*   ei  = (const int*)d_in[1];
    // d_in[2] = edge_attr (unused; GATConv edge_dim=None)
    const float* W1  = (const float*)d_in[3];
    const float* as1 = (const float*)d_in[4];
    const float* ad1 = (const float*)d_in[5];
    const float* b1  = (const float*)d_in[6];
    const float* W2  = (const float*)d_in[7];
    const float* as2 = (const float*)d_in[8];
    const float* ad2 = (const float*)d_in[9];
    const float* b2  = (const float*)d_in[10];
    float* out = (float*)d_out;

    // CSR build (reused by both layers)
    k_init<<<392, 256>>>(out);
    k_hist<<<6250, 256>>>(ei);
    k_scan1<<<NB_SCAN, 1024>>>();
    k_scan2<<<1, 32>>>();
    k_scan3<<<NB_SCAN, 1024>>>();
    k_fill<<<6250, 256>>>(ei);

    // layer 1
    k_gemm<128><<<3125, 256>>>(x, W1, as1, ad1);
    k_agg<<<12500, 256>>>(b1, 1);

    // layer 2 (reads g_feat internally)
    k_gemm<64><<<3125, 256>>>(nullptr, W2, as2, ad2);
    k_agg<<<12500, 256>>>(b2, 0);

    // mean pool
    k_mean<<<256, 256>>>(out);
}

// round 2
// speedup vs baseline: 1.5015x; 1.5015x over previous
#include <cuda_runtime.h>

#define N_NODES 100000
#define N_EDGES 1600000
#define NB_SCAN 98              // ceil((N_NODES+1)/1024)
#define NEG_SLOPE 0.2f
#define FULLM 0xffffffffu

// ---------------- scratch (device globals; no allocation allowed) ----------------
__device__ int   g_deg[N_NODES + 1];
__device__ int   g_rowptr[N_NODES + 1];
__device__ int   g_cursor[N_NODES];
__device__ int   g_bsum[128];
__device__ int   g_adj[N_EDGES];
__device__ float g_h[N_NODES * 64];      // current layer transformed features
__device__ float g_feat[N_NODES * 64];   // aggregated layer-1 output (input to layer 2)
__device__ float g_as[N_NODES];
__device__ float g_ad[N_NODES];

// ---------------- init: zero degree histogram + output ----------------
__global__ void k_init(float* __restrict__ out) {
    int i = blockIdx.x * blockDim.x + threadIdx.x;
    if (i <= N_NODES) g_deg[i] = 0;
    if (i < 64) out[i] = 0.0f;
}

// ---------------- degree histogram over dst ----------------
__global__ void k_hist(const int* __restrict__ ei) {
    int e = blockIdx.x * blockDim.x + threadIdx.x;
    if (e < N_EDGES) atomicAdd(&g_deg[ei[N_EDGES + e] + 1], 1);
}

// ---------------- scan of g_deg -> g_rowptr (block scan + warp mid-scan) ----------------
__global__ void k_scan1() {
    __shared__ int s[1024];
    int t = threadIdx.x;
    int i = blockIdx.x * 1024 + t;
    int v = (i <= N_NODES) ? g_deg[i] : 0;
    s[t] = v;
    __syncthreads();
    for (int off = 1; off < 1024; off <<= 1) {
        int x = (t >= off) ? s[t - off] : 0;
        __syncthreads();
        s[t] += x;
        __syncthreads();
    }
    if (i <= N_NODES) g_rowptr[i] = s[t];
    if (t == 1023) g_bsum[blockIdx.x] = s[1023];
}

// one-warp exclusive scan of the 98 block sums
__global__ void k_scan2() {
    int lane = threadIdx.x;
    int run = 0;
    for (int base = 0; base < NB_SCAN; base += 32) {
        int i = base + lane;
        int v = (i < NB_SCAN) ? g_bsum[i] : 0;
        int inc = v;
#pragma unroll
        for (int m = 1; m < 32; m <<= 1) {
            int t = __shfl_up_sync(FULLM, inc, m);
            if (lane >= m) inc += t;
        }
        if (i < NB_SCAN) g_bsum[i] = inc - v + run;
        run += __shfl_sync(FULLM, inc, 31);
    }
}

__global__ void k_scan3() {
    int i = blockIdx.x * 1024 + threadIdx.x;
    if (i <= N_NODES) {
        int v = g_rowptr[i] + g_bsum[blockIdx.x];
        g_rowptr[i] = v;
        if (i < N_NODES) g_cursor[i] = v;
    }
}

// ---------------- fill adjacency (src indices grouped by dst) ----------------
__global__ void k_fill(const int* __restrict__ ei) {
    int e = blockIdx.x * blockDim.x + threadIdx.x;
    if (e < N_EDGES) {
        int d = ei[N_EDGES + e];
        int pos = atomicAdd(&g_cursor[d], 1);
        g_adj[pos] = ei[e];
    }
}

// ---------------- fused GEMM (h = X @ W^T) + attention logits ----------------
// Block = 256 threads = 64 nodes. Thread (ng = tid>>4, og = tid&15) computes a
// 4-node x 4-output register tile: nodes n0..n0+3, outputs og*4..og*4+3.
// The 16 lanes of a half-warp share the same 4 node rows -> x loads broadcast.
// 8 LDG.128 per 64 FMAs -> FMA-pipe bound.
template <int IN>
__global__ void __launch_bounds__(256)
k_gemm(const float* __restrict__ Xext,
       const float* __restrict__ W,
       const float* __restrict__ avsrc,
       const float* __restrict__ avdst) {
    const float* X = (IN == 128) ? Xext : (const float*)g_feat;
    const int tid = threadIdx.x;
    const int og  = tid & 15;
    const int ng  = tid >> 4;
    const int n0  = blockIdx.x * 64 + ng * 4;
    const int C   = IN / 4;

    const int nb = min(n0, N_NODES - 4);          // clamp for tail-block loads
    const float4* x = (const float4*)X + (long)nb * C;
    const float4* w = (const float4*)W + (long)(og * 4) * C;

    float acc[4][4];
#pragma unroll
    for (int i = 0; i < 4; i++)
#pragma unroll
        for (int o = 0; o < 4; o++) acc[i][o] = 0.f;

    for (int c = 0; c < C; c++) {
        float4 wv[4], xv[4];
#pragma unroll
        for (int o = 0; o < 4; o++) wv[o] = __ldg(w + o * C + c);
#pragma unroll
        for (int i = 0; i < 4; i++) xv[i] = __ldg(x + i * C + c);
#pragma unroll
        for (int i = 0; i < 4; i++)
#pragma unroll
            for (int o = 0; o < 4; o++)
                acc[i][o] += xv[i].x * wv[o].x + xv[i].y * wv[o].y +
                             xv[i].z * wv[o].z + xv[i].w * wv[o].w;
    }

    float4* H4 = (float4*)g_h;
#pragma unroll
    for (int i = 0; i < 4; i++)
        if (n0 + i < N_NODES)
            H4[(long)(n0 + i) * 16 + og] =
                make_float4(acc[i][0], acc[i][1], acc[i][2], acc[i][3]);

    // attention logit partials: as = h . a_src, ad = h . a_dst
    float4 sv = __ldg((const float4*)avsrc + og);
    float4 dv = __ldg((const float4*)avdst + og);

    float asv[4], adv[4];
#pragma unroll
    for (int i = 0; i < 4; i++) {
        float sp = acc[i][0] * sv.x + acc[i][1] * sv.y + acc[i][2] * sv.z + acc[i][3] * sv.w;
        float dp = acc[i][0] * dv.x + acc[i][1] * dv.y + acc[i][2] * dv.z + acc[i][3] * dv.w;
#pragma unroll
        for (int m = 8; m; m >>= 1) {
            sp += __shfl_xor_sync(FULLM, sp, m);
            dp += __shfl_xor_sync(FULLM, dp, m);
        }
        asv[i] = sp; adv[i] = dp;
    }
    if (og == 0) {
#pragma unroll
        for (int i = 0; i < 4; i++)
            if (n0 + i < N_NODES) { g_as[n0 + i] = asv[i]; g_ad[n0 + i] = adv[i]; }
    }
}

// ---------------- warp-per-node softmax aggregation (atomic-free) ----------------
// exp-max subtraction omitted: logits are O(10), exp cannot overflow in fp32
// and the normalized ratio is mathematically unchanged.
// Broadcast loop unrolled x4 -> 8 independent gathers in flight (MLP 8).
// mode 1: relu + store g_feat (layer 1); mode 2: fold global mean pool (layer 2).
__global__ void __launch_bounds__(512)
k_agg(const float* __restrict__ b, float* __restrict__ out, int mode) {
    __shared__ float sred[64];
    if (threadIdx.x < 64) sred[threadIdx.x] = 0.f;
    __syncthreads();

    const int node = (blockIdx.x * blockDim.x + threadIdx.x) >> 5;   // grid covers exactly N_NODES warps
    const int lane = threadIdx.x & 31;

    float adn = g_ad[node];
    float e0 = g_as[node] + adn;
    e0 = (e0 > 0.f) ? e0 : NEG_SLOPE * e0;
    float exs = __expf(e0);                       // self-loop term

    float acc0 = exs * g_h[node * 64 + lane];
    float acc1 = exs * g_h[node * 64 + 32 + lane];
    float dsum = 0.f;

    const int beg = g_rowptr[node];
    const int end = g_rowptr[node + 1];
    for (int k = beg; k < end; k += 32) {
        int idx = k + lane;
        int s = 0;
        float ex = 0.f;
        if (idx < end) {
            s = __ldg(&g_adj[idx]);
            float e = __ldg(&g_as[s]) + adn;
            e = (e > 0.f) ? e : NEG_SLOPE * e;
            ex = __expf(e);
        }
        dsum += ex;
        const int cnt = min(32, end - k);
        int j = 0;
        for (; j + 4 <= cnt; j += 4) {
            int   s0 = __shfl_sync(FULLM, s, j);
            int   s1 = __shfl_sync(FULLM, s, j + 1);
            int   s2 = __shfl_sync(FULLM, s, j + 2);
            int   s3 = __shfl_sync(FULLM, s, j + 3);
            float x0 = __shfl_sync(FULLM, ex, j);
            float x1 = __shfl_sync(FULLM, ex, j + 1);
            float x2 = __shfl_sync(FULLM, ex, j + 2);
            float x3 = __shfl_sync(FULLM, ex, j + 3);
            float h00 = __ldg(&g_h[s0 * 64 + lane]);
            float h01 = __ldg(&g_h[s0 * 64 + 32 + lane]);
            float h10 = __ldg(&g_h[s1 * 64 + lane]);
            float h11 = __ldg(&g_h[s1 * 64 + 32 + lane]);
            float h20 = __ldg(&g_h[s2 * 64 + lane]);
            float h21 = __ldg(&g_h[s2 * 64 + 32 + lane]);
            float h30 = __ldg(&g_h[s3 * 64 + lane]);
            float h31 = __ldg(&g_h[s3 * 64 + 32 + lane]);
            acc0 += x0 * h00; acc1 += x0 * h01;
            acc0 += x1 * h10; acc1 += x1 * h11;
            acc0 += x2 * h20; acc1 += x2 * h21;
            acc0 += x3 * h30; acc1 += x3 * h31;
        }
        for (; j < cnt; j++) {
            int   sj = __shfl_sync(FULLM, s, j);
            float xj = __shfl_sync(FULLM, ex, j);
            acc0 += xj * __ldg(&g_h[sj * 64 + lane]);
            acc1 += xj * __ldg(&g_h[sj * 64 + 32 + lane]);
        }
    }
#pragma unroll
    for (int m = 16; m; m >>= 1) dsum += __shfl_xor_sync(FULLM, dsum, m);

    float inv = 1.0f / (dsum + exs);
    float r0 = acc0 * inv + __ldg(&b[lane]);
    float r1 = acc1 * inv + __ldg(&b[lane + 32]);

    if (mode == 1) {
        r0 = fmaxf(r0, 0.f); r1 = fmaxf(r1, 0.f);
        g_feat[node * 64 + lane] = r0;
        g_feat[node * 64 + 32 + lane] = r1;
    } else {
        // fused global mean pool: block partial -> single atomic per feature
        atomicAdd(&sred[lane], r0);
        atomicAdd(&sred[lane + 32], r1);
        __syncthreads();
        if (threadIdx.x < 64)
            atomicAdd(&out[threadIdx.x], sred[threadIdx.x] * (1.0f / N_NODES));
    }
}

// ---------------- launch ----------------
extern "C" void kernel_launch(void* const* d_in, const int* in_sizes, int n_in,
                              void* d_out, int out_size) {
    const float* x   = (const float*)d_in[0];
    const int*   ei  = (const int*)d_in[1];
    // d_in[2] = edge_attr (unused; GATConv edge_dim=None)
    const float* W1  = (const float*)d_in[3];
    const float* as1 = (const float*)d_in[4];
    const float* ad1 = (const float*)d_in[5];
    const float* b1  = (const float*)d_in[6];
    const float* W2  = (const float*)d_in[7];
    const float* as2 = (const float*)d_in[8];
    const float* ad2 = (const float*)d_in[9];
    const float* b2  = (const float*)d_in[10];
    float* out = (float*)d_out;

    // CSR build (reused by both layers)
    k_init<<<392, 256>>>(out);
    k_hist<<<3125, 512>>>(ei);
    k_scan1<<<NB_SCAN, 1024>>>();
    k_scan2<<<1, 32>>>();
    k_scan3<<<NB_SCAN, 1024>>>();
    k_fill<<<3125, 512>>>(ei);

    // layer 1
    k_gemm<128><<<1563, 256>>>(x, W1, as1, ad1);
    k_agg<<<6250, 512>>>(b1, out, 1);

    // layer 2 (reads g_feat internally; mean pool fused)
    k_gemm<64><<<1563, 256>>>(nullptr, W2, as2, ad2);
    k_agg<<<6250, 512>>>(b2, out, 2);
}

// round 3
// speedup vs baseline: 1.6184x; 1.0778x over previous
#include <cuda_runtime.h>

#define N_NODES 100000
#define N_EDGES 1600000
#define NB_SCAN 98              // ceil((N_NODES+1)/1024)
#define NEG_SLOPE 0.2f
#define FULLM 0xffffffffu
#define GB_GEMM 1563            // ceil(N_NODES/64)
#define GB_HIST 6250            // ceil(N_EDGES/256)

// ---------------- scratch (device globals; zero-initialized at module load) ----------
// Cross-call invariant: g_deg and g_tstat are zero at the start of every
// kernel_launch call — guaranteed by module-load zero-init for the first call
// and re-zeroed inside k_fill (after their last use) for every later call.
__device__ int      g_deg[N_NODES + 1];
__device__ int      g_rowptr[N_NODES + 1];
__device__ int      g_cursor[N_NODES];
__device__ unsigned g_tstat[NB_SCAN];     // lookback status: [31:30] flag (1=agg,2=prefix), [29:0] value
__device__ int      g_adj[N_EDGES];
__device__ float    g_h[N_NODES * 64];    // transformed features of current layer
__device__ float    g_feat[N_NODES * 64]; // layer-1 output (input to layer 2)
__device__ float    g_as[N_NODES];
__device__ float    g_ad[N_NODES];

// ---------------- fused GEMM (h = X @ W^T) + attention logits [+ dst histogram] -------
// gemm part: block = 256 threads = 64 nodes. Thread (ng = tid>>4, og = tid&15)
// computes a 4-node x 4-output register tile. 16 lanes share node rows -> x
// loads broadcast in L1. 8 LDG.128 per 64 FFMA -> FMA-pipe bound.
// HIST: blocks >= GB_GEMM compute the dst-degree histogram (LSU-bound, overlaps
// the FMA-bound gemm blocks for free).
template <int IN, bool HIST>
__global__ void __launch_bounds__(256)
k_gemm(const float* __restrict__ Xext,
       const float* __restrict__ W,
       const float* __restrict__ avsrc,
       const float* __restrict__ avdst,
       const int* __restrict__ ei,
       float* __restrict__ out) {
    if (HIST && blockIdx.x >= GB_GEMM) {
        int e = (blockIdx.x - GB_GEMM) * 256 + threadIdx.x;
        if (e < N_EDGES) atomicAdd(&g_deg[ei[N_EDGES + e] + 1], 1);
        return;
    }
    if (!HIST && blockIdx.x == 0 && threadIdx.x < 64) out[threadIdx.x] = 0.0f;

    const float* X = (IN == 128) ? Xext : (const float*)g_feat;
    const int tid = threadIdx.x;
    const int og  = tid & 15;
    const int ng  = tid >> 4;
    const int n0  = blockIdx.x * 64 + ng * 4;
    const int C   = IN / 4;

    const int nb = min(n0, N_NODES - 4);          // clamp for tail-block loads
    const float4* x = (const float4*)X + (long)nb * C;
    const float4* w = (const float4*)W + (long)(og * 4) * C;

    float acc[4][4];
#pragma unroll
    for (int i = 0; i < 4; i++)
#pragma unroll
        for (int o = 0; o < 4; o++) acc[i][o] = 0.f;

    for (int c = 0; c < C; c++) {
        float4 wv[4], xv[4];
#pragma unroll
        for (int o = 0; o < 4; o++) wv[o] = __ldg(w + o * C + c);
#pragma unroll
        for (int i = 0; i < 4; i++) xv[i] = __ldg(x + i * C + c);
#pragma unroll
        for (int i = 0; i < 4; i++)
#pragma unroll
            for (int o = 0; o < 4; o++)
                acc[i][o] += xv[i].x * wv[o].x + xv[i].y * wv[o].y +
                             xv[i].z * wv[o].z + xv[i].w * wv[o].w;
    }

    float4* H4 = (float4*)g_h;
#pragma unroll
    for (int i = 0; i < 4; i++)
        if (n0 + i < N_NODES)
            H4[(long)(n0 + i) * 16 + og] =
                make_float4(acc[i][0], acc[i][1], acc[i][2], acc[i][3]);

    // attention logit partials: as = h . a_src, ad = h . a_dst
    float4 sv = __ldg((const float4*)avsrc + og);
    float4 dv = __ldg((const float4*)avdst + og);

    float asv[4], adv[4];
#pragma unroll
    for (int i = 0; i < 4; i++) {
        float sp = acc[i][0] * sv.x + acc[i][1] * sv.y + acc[i][2] * sv.z + acc[i][3] * sv.w;
        float dp = acc[i][0] * dv.x + acc[i][1] * dv.y + acc[i][2] * dv.z + acc[i][3] * dv.w;
#pragma unroll
        for (int m = 8; m; m >>= 1) {
            sp += __shfl_xor_sync(FULLM, sp, m);
            dp += __shfl_xor_sync(FULLM, dp, m);
        }
        asv[i] = sp; adv[i] = dp;
    }
    if (og == 0) {
#pragma unroll
        for (int i = 0; i < 4; i++)
            if (n0 + i < N_NODES) { g_as[n0 + i] = asv[i]; g_ad[n0 + i] = adv[i]; }
    }
}

// ---------------- single-kernel decoupled-lookback scan of g_deg -> g_rowptr ----------
// 98 tiles of 1024; grid of 98 blocks is fully co-resident (98 < 148 SMs) so
// polling always makes progress. Status word packs flag+value (values < 2^21)
// so a single 32-bit atomic publish needs no separate fence.
__global__ void __launch_bounds__(1024) k_scan() {
    __shared__ int s[1024];
    __shared__ int s_prefix;
    const int t = threadIdx.x;
    const int tile = blockIdx.x;
    const int i = tile * 1024 + t;
    int v = (i <= N_NODES) ? g_deg[i] : 0;
    s[t] = v;
    __syncthreads();
    for (int off = 1; off < 1024; off <<= 1) {
        int x = (t >= off) ? s[t - off] : 0;
        __syncthreads();
        s[t] += x;
        __syncthreads();
    }
    const int inc = s[t];
    const int total = s[1023];

    if (t == 0) {
        if (tile == 0) {
            atomicExch(&g_tstat[0], (2u << 30) | (unsigned)total);
            s_prefix = 0;
        } else {
            atomicExch(&g_tstat[tile], (1u << 30) | (unsigned)total);
            int prefix = 0;
            int p = tile - 1;
            while (true) {
                unsigned st = *(volatile unsigned*)&g_tstat[p];
                unsigned f = st >> 30;
                if (f == 0u) continue;
                prefix += (int)(st & 0x3FFFFFFFu);
                if (f == 2u) break;
                p--;
            }
            atomicExch(&g_tstat[tile], (2u << 30) | (unsigned)(prefix + total));
            s_prefix = prefix;
        }
    }
    __syncthreads();
    const int val = inc + s_prefix;
    if (i <= N_NODES) {
        g_rowptr[i] = val;
        if (i < N_NODES) g_cursor[i] = val;
    }
}

// ---------------- fill adjacency (src grouped by dst) + cleanup for next call --------
__global__ void __launch_bounds__(512) k_fill(const int* __restrict__ ei) {
    int gid = blockIdx.x * 512 + threadIdx.x;
    if (gid <= N_NODES) g_deg[gid] = 0;       // reset for next kernel_launch call
    if (gid < NB_SCAN) g_tstat[gid] = 0u;     // reset lookback status
    if (gid < N_EDGES) {
        int d = ei[N_EDGES + gid];
        int pos = atomicAdd(&g_cursor[d], 1);
        g_adj[pos] = ei[gid];
    }
}

// ---------------- half-warp-per-node softmax aggregation (atomic-free) ---------------
// 16 lanes own one node; lane l holds features [4l, 4l+4). One LDG.128 across
// the 16 lanes fetches a full 256B h-row per edge. exp-max subtraction omitted:
// logits are O(10) so fp32 exp cannot overflow and the ratio is unchanged.
// mode 1: relu + store g_feat; mode 2: fused global mean pool into out.
__global__ void __launch_bounds__(512)
k_agg(const float* __restrict__ b, float* __restrict__ out, int mode) {
    __shared__ float sred[64];
    if (mode == 2) {
        if (threadIdx.x < 64) sred[threadIdx.x] = 0.f;
        __syncthreads();
    }
    const int lane = threadIdx.x & 31;
    const int l = lane & 15;
    const unsigned hm = 0xFFFFu << (lane & 16);
    const int node = (blockIdx.x * 512 + threadIdx.x) >> 4;   // exact: 3125*512/16 = 100000

    const float4* H4 = (const float4*)g_h;
    const float adn = g_ad[node];
    float e0 = g_as[node] + adn;
    e0 = (e0 > 0.f) ? e0 : NEG_SLOPE * e0;
    const float exs = __expf(e0);                 // self-loop term

    float4 hv = __ldg(H4 + (long)node * 16 + l);
    float4 acc = make_float4(exs * hv.x, exs * hv.y, exs * hv.z, exs * hv.w);
    float dsum = 0.f;

    const int beg = g_rowptr[node];
    const int end = g_rowptr[node + 1];
    for (int k = beg; k < end; k += 16) {
        int idx = k + l;
        int s = 0;
        float ex = 0.f;
        if (idx < end) {
            s = __ldg(&g_adj[idx]);
            float e = __ldg(&g_as[s]) + adn;
            e = (e > 0.f) ? e : NEG_SLOPE * e;
            ex = __expf(e);
        }
        dsum += ex;
        const int cnt = min(16, end - k);
        int j = 0;
        for (; j + 4 <= cnt; j += 4) {
            int   s0 = __shfl_sync(hm, s, j, 16);
            int   s1 = __shfl_sync(hm, s, j + 1, 16);
            int   s2 = __shfl_sync(hm, s, j + 2, 16);
            int   s3 = __shfl_sync(hm, s, j + 3, 16);
            float x0 = __shfl_sync(hm, ex, j, 16);
            float x1 = __shfl_sync(hm, ex, j + 1, 16);
            float x2 = __shfl_sync(hm, ex, j + 2, 16);
            float x3 = __shfl_sync(hm, ex, j + 3, 16);
            float4 h0 = __ldg(H4 + (long)s0 * 16 + l);
            float4 h1 = __ldg(H4 + (long)s1 * 16 + l);
            float4 h2 = __ldg(H4 + (long)s2 * 16 + l);
            float4 h3 = __ldg(H4 + (long)s3 * 16 + l);
            acc.x += x0 * h0.x; acc.y += x0 * h0.y; acc.z += x0 * h0.z; acc.w += x0 * h0.w;
            acc.x += x1 * h1.x; acc.y += x1 * h1.y; acc.z += x1 * h1.z; acc.w += x1 * h1.w;
            acc.x += x2 * h2.x; acc.y += x2 * h2.y; acc.z += x2 * h2.z; acc.w += x2 * h2.w;
            acc.x += x3 * h3.x; acc.y += x3 * h3.y; acc.z += x3 * h3.z; acc.w += x3 * h3.w;
        }
        for (; j < cnt; j++) {
            int   sj = __shfl_sync(hm, s, j, 16);
            float xj = __shfl_sync(hm, ex, j, 16);
            float4 hj = __ldg(H4 + (long)sj * 16 + l);
            acc.x += xj * hj.x; acc.y += xj * hj.y; acc.z += xj * hj.z; acc.w += xj * hj.w;
        }
    }
#pragma unroll
    for (int m = 8; m; m >>= 1) dsum += __shfl_xor_sync(hm, dsum, m, 16);

    const float inv = 1.0f / (dsum + exs);
    float4 bb = __ldg((const float4*)b + l);
    float4 r = make_float4(acc.x * inv + bb.x, acc.y * inv + bb.y,
                           acc.z * inv + bb.z, acc.w * inv + bb.w);

    if (mode == 1) {
        r.x = fmaxf(r.x, 0.f); r.y = fmaxf(r.y, 0.f);
        r.z = fmaxf(r.z, 0.f); r.w = fmaxf(r.w, 0.f);
        ((float4*)g_feat)[(long)node * 16 + l] = r;
    } else {
        // fused global mean pool: combine the warp's two nodes (lanes l, l+16
        // hold the same feature), then spread-address shared atomics.
        __syncwarp(FULLM);
        r.x += __shfl_xor_sync(FULLM, r.x, 16);
        r.y += __shfl_xor_sync(FULLM, r.y, 16);
        r.z += __shfl_xor_sync(FULLM, r.z, 16);
        r.w += __shfl_xor_sync(FULLM, r.w, 16);
        if (lane < 16) {
            atomicAdd(&sred[4 * l + 0], r.x);
            atomicAdd(&sred[4 * l + 1], r.y);
            atomicAdd(&sred[4 * l + 2], r.z);
            atomicAdd(&sred[4 * l + 3], r.w);
        }
        __syncthreads();
        if (threadIdx.x < 64)
            atomicAdd(&out[threadIdx.x], sred[threadIdx.x] * (1.0f / N_NODES));
    }
}

// ---------------- launch ----------------
extern "C" void kernel_launch(void* const* d_in, const int* in_sizes, int n_in,
                              void* d_out, int out_size) {
    const float* x   = (const float*)d_in[0];
    const int*   ei  = (const int*)d_in[1];
    // d_in[2] = edge_attr (unused; GATConv edge_dim=None)
    const float* W1  = (const float*)d_in[3];
    const float* as1 = (const float*)d_in[4];
    const float* ad1 = (const float*)d_in[5];
    const float* b1  = (const float*)d_in[6];
    const float* W2  = (const float*)d_in[7];
    const float* as2 = (const float*)d_in[8];
    const float* ad2 = (const float*)d_in[9];
    const float* b2  = (const float*)d_in[10];
    float* out = (float*)d_out;

    // (0) layer-1 gemm + dst histogram (fused, complementary pipes)
    k_gemm<128, true><<<GB_GEMM + GB_HIST, 256>>>(x, W1, as1, ad1, ei, out);
    // (1) rowptr via single-kernel decoupled lookback scan
    k_scan<<<NB_SCAN, 1024>>>();
    // (2) adjacency fill + scratch reset for next call
    k_fill<<<3125, 512>>>(ei);
    // (3) layer-1 aggregation  <- profiled launch
    k_agg<<<3125, 512>>>(b1, out, 1);
    // (4) layer-2 gemm (+ zero out)
    k_gemm<64, false><<<GB_GEMM, 256>>>(nullptr, W2, as2, ad2, nullptr, out);
    // (5) layer-2 aggregation + fused global mean pool
    k_agg<<<3125, 512>>>(b2, out, 2);
}

// round 4
// speedup vs baseline: 3.2978x; 2.0378x over previous
#include <cuda_runtime.h>

#define N_NODES 100000
#define N_EDGES 1600000
#define NB_SCAN 98              // ceil((N_NODES+1)/1024)
#define NEG_SLOPE 0.2f
#define FULLM 0xffffffffu
#define GB_GEMM 1563            // ceil(N_NODES/64)
#define GB_HIST 6250            // ceil(N_EDGES/256)

// ---------------- scratch (device globals; zero-initialized at module load) ----------
// Cross-call invariant: g_deg and g_tstat are zero at the start of every
// kernel_launch call — module-load zero-init covers the first call; k_fill
// re-zeroes them (after their last use) for every later call.
__device__ int      g_deg[N_NODES + 1];
__device__ int      g_rowptr[N_NODES + 1];
__device__ int      g_cursor[N_NODES];
__device__ unsigned g_tstat[NB_SCAN];     // lookback status: [31:30] flag (1=agg,2=prefix), [29:0] value
__device__ int      g_adj[N_EDGES];
__device__ float    g_h[N_NODES * 64];    // transformed features of current layer
__device__ float    g_feat[N_NODES * 64]; // layer-1 output (input to layer 2)
__device__ float    g_as[N_NODES];
__device__ float    g_ad[N_NODES];

// ---------------- smem-staged SIMT outer-product GEMM + attention logits -------------
// Block = 256 threads -> tile of 64 nodes x 64 outputs. Thread (tx=tid&15,
// ty=tid>>4) owns a 4x4 register tile: nodes tx*4..+3, outs ty*4..+3.
// X tile and W are transposed into k-major smem; inner loop per k is
// 2x LDS.128 (conflict-light) + 16 FFMA -> FFMA-pipe bound (the previous
// version burned 32 L1 wavefronts per W load: 16 lanes x 512B row stride).
// HIST: extra blocks compute the dst-degree histogram (LSU-bound, overlaps).
template <int IN, bool HIST>
__global__ void __launch_bounds__(256)
k_gemm(const float* __restrict__ Xext,
       const float* __restrict__ W,
       const float* __restrict__ avsrc,
       const float* __restrict__ avdst,
       const int* __restrict__ ei,
       float* __restrict__ out) {
    if (HIST && blockIdx.x >= GB_GEMM) {
        int e = (blockIdx.x - GB_GEMM) * 256 + threadIdx.x;
        if (e < N_EDGES) atomicAdd(&g_deg[ei[N_EDGES + e] + 1], 1);
        return;
    }
    __shared__ float xs[64][68];     // xs[k][node]
    __shared__ float ws[64][68];     // ws[k][out]
    __shared__ float sASP[64][17];   // per-node logit partials over ty
    __shared__ float sADP[64][17];

    const float* X = (IN == 128) ? Xext : (const float*)g_feat;
    const int tid = threadIdx.x;
    const int tx  = tid & 15;
    const int ty  = tid >> 4;
    const int nbase = blockIdx.x * 64;
    const int C = IN / 4;            // float4s per row

    if (!HIST && blockIdx.x == 0 && tid < 64) out[tid] = 0.0f;

    const float4* X4 = (const float4*)X;
    const float4* W4 = (const float4*)W;

    float acc[4][4];
#pragma unroll
    for (int i = 0; i < 4; i++)
#pragma unroll
        for (int o = 0; o < 4; o++) acc[i][o] = 0.f;

#pragma unroll
    for (int ch = 0; ch < IN / 64; ch++) {
        const int kc4 = ch * 16;     // float4 column offset of this k-chunk
        __syncthreads();
        // stage X-tile and W chunk, transposing to k-major.
        // idx bits: [1:0]->c4 low, [7:2]->row, [9:8]->c4 high
        // -> warp covers 8 rows x 4 c4: 64B-coalesced global reads, 2-way STS banks.
#pragma unroll
        for (int it = 0; it < 4; it++) {
            int idx = tid + it * 256;
            int c4  = (idx & 3) | (((idx >> 8) & 3) << 2);
            int r   = (idx >> 2) & 63;
            int xrow = min(nbase + r, N_NODES - 1);     // clamp tail (stores guarded)
            float4 v = __ldg(&X4[(long)xrow * C + kc4 + c4]);
            xs[c4 * 4 + 0][r] = v.x; xs[c4 * 4 + 1][r] = v.y;
            xs[c4 * 4 + 2][r] = v.z; xs[c4 * 4 + 3][r] = v.w;
            float4 wv = __ldg(&W4[(long)r * C + kc4 + c4]);
            ws[c4 * 4 + 0][r] = wv.x; ws[c4 * 4 + 1][r] = wv.y;
            ws[c4 * 4 + 2][r] = wv.z; ws[c4 * 4 + 3][r] = wv.w;
        }
        __syncthreads();

#pragma unroll 4
        for (int kk = 0; kk < 64; kk++) {
            float4 xv = *(const float4*)&xs[kk][tx * 4];   // 4 nodes at this k
            float4 wv = *(const float4*)&ws[kk][ty * 4];   // 4 outs at this k
            acc[0][0] += xv.x * wv.x; acc[0][1] += xv.x * wv.y;
            acc[0][2] += xv.x * wv.z; acc[0][3] += xv.x * wv.w;
            acc[1][0] += xv.y * wv.x; acc[1][1] += xv.y * wv.y;
            acc[1][2] += xv.y * wv.z; acc[1][3] += xv.y * wv.w;
            acc[2][0] += xv.z * wv.x; acc[2][1] += xv.z * wv.y;
            acc[2][2] += xv.z * wv.z; acc[2][3] += xv.z * wv.w;
            acc[3][0] += xv.w * wv.x; acc[3][1] += xv.w * wv.y;
            acc[3][2] += xv.w * wv.z; acc[3][3] += xv.w * wv.w;
        }
    }

    // store h
    float4* H4 = (float4*)g_h;
#pragma unroll
    for (int i = 0; i < 4; i++) {
        int node = nbase + tx * 4 + i;
        if (node < N_NODES)
            H4[(long)node * 16 + ty] =
                make_float4(acc[i][0], acc[i][1], acc[i][2], acc[i][3]);
    }

    // attention logit partials: as = h . a_src, ad = h . a_dst (deterministic tree)
    float4 sv = __ldg((const float4*)avsrc + ty);
    float4 dv = __ldg((const float4*)avdst + ty);
#pragma unroll
    for (int i = 0; i < 4; i++) {
        float sp = acc[i][0] * sv.x + acc[i][1] * sv.y + acc[i][2] * sv.z + acc[i][3] * sv.w;
        float dp = acc[i][0] * dv.x + acc[i][1] * dv.y + acc[i][2] * dv.z + acc[i][3] * dv.w;
        sASP[tx * 4 + i][ty] = sp;
        sADP[tx * 4 + i][ty] = dp;
    }
    __syncthreads();
    if (tid < 64) {
        int node = nbase + tid;
        if (node < N_NODES) {
            float s = 0.f, d = 0.f;
#pragma unroll
            for (int j = 0; j < 16; j++) { s += sASP[tid][j]; d += sADP[tid][j]; }
            g_as[node] = s;
            g_ad[node] = d;
        }
    }
}

// ---------------- single-kernel decoupled-lookback scan of g_deg -> g_rowptr ----------
__global__ void __launch_bounds__(1024) k_scan() {
    __shared__ int s[1024];
    __shared__ int s_prefix;
    const int t = threadIdx.x;
    const int tile = blockIdx.x;
    const int i = tile * 1024 + t;
    int v = (i <= N_NODES) ? g_deg[i] : 0;
    s[t] = v;
    __syncthreads();
    for (int off = 1; off < 1024; off <<= 1) {
        int x = (t >= off) ? s[t - off] : 0;
        __syncthreads();
        s[t] += x;
        __syncthreads();
    }
    const int inc = s[t];
    const int total = s[1023];

    if (t == 0) {
        if (tile == 0) {
            atomicExch(&g_tstat[0], (2u << 30) | (unsigned)total);
            s_prefix = 0;
        } else {
            atomicExch(&g_tstat[tile], (1u << 30) | (unsigned)total);
            int prefix = 0;
            int p = tile - 1;
            while (true) {
                unsigned st = *(volatile unsigned*)&g_tstat[p];
                unsigned f = st >> 30;
                if (f == 0u) continue;
                prefix += (int)(st & 0x3FFFFFFFu);
                if (f == 2u) break;
                p--;
            }
            atomicExch(&g_tstat[tile], (2u << 30) | (unsigned)(prefix + total));
            s_prefix = prefix;
        }
    }
    __syncthreads();
    const int val = inc + s_prefix;
    if (i <= N_NODES) {
        g_rowptr[i] = val;
        if (i < N_NODES) g_cursor[i] = val;
    }
}

// ---------------- fill adjacency (src grouped by dst) + cleanup for next call --------
__global__ void __launch_bounds__(512) k_fill(const int* __restrict__ ei) {
    int gid = blockIdx.x * 512 + threadIdx.x;
    if (gid <= N_NODES) g_deg[gid] = 0;       // reset for next kernel_launch call
    if (gid < NB_SCAN) g_tstat[gid] = 0u;     // reset lookback status
    if (gid < N_EDGES) {
        int d = ei[N_EDGES + gid];
        int pos = atomicAdd(&g_cursor[d], 1);
        g_adj[pos] = ei[gid];
    }
}

// ---------------- half-warp-per-node softmax aggregation (atomic-free) ---------------
// 16 lanes own one node; lane l holds features [4l, 4l+4). One LDG.128 across
// the 16 lanes fetches a full 256B h-row per edge. exp-max subtraction omitted:
// logits are O(10) so fp32 exp cannot overflow and the ratio is unchanged.
// mode 1: relu + store g_feat; mode 2: fused global mean pool into out.
__global__ void __launch_bounds__(512)
k_agg(const float* __restrict__ b, float* __restrict__ out, int mode) {
    __shared__ float sred[64];
    if (mode == 2) {
        if (threadIdx.x < 64) sred[threadIdx.x] = 0.f;
        __syncthreads();
    }
    const int lane = threadIdx.x & 31;
    const int l = lane & 15;
    const unsigned hm = 0xFFFFu << (lane & 16);
    const int node = (blockIdx.x * 512 + threadIdx.x) >> 4;   // exact: 3125*512/16 = 100000

    const float4* H4 = (const float4*)g_h;
    const float adn = g_ad[node];
    float e0 = g_as[node] + adn;
    e0 = (e0 > 0.f) ? e0 : NEG_SLOPE * e0;
    const float exs = __expf(e0);                 // self-loop term

    float4 hv = __ldg(H4 + (long)node * 16 + l);
    float4 acc = make_float4(exs * hv.x, exs * hv.y, exs * hv.z, exs * hv.w);
    float dsum = 0.f;

    const int beg = g_rowptr[node];
    const int end = g_rowptr[node + 1];
    for (int k = beg; k < end; k += 16) {
        int idx = k + l;
        int s = 0;
        float ex = 0.f;
        if (idx < end) {
            s = __ldg(&g_adj[idx]);
            float e = __ldg(&g_as[s]) + adn;
            e = (e > 0.f) ? e : NEG_SLOPE * e;
            ex = __expf(e);
        }
        dsum += ex;
        const int cnt = min(16, end - k);
        int j = 0;
        for (; j + 4 <= cnt; j += 4) {
            int   s0 = __shfl_sync(hm, s, j, 16);
            int   s1 = __shfl_sync(hm, s, j + 1, 16);
            int   s2 = __shfl_sync(hm, s, j + 2, 16);
            int   s3 = __shfl_sync(hm, s, j + 3, 16);
            float x0 = __shfl_sync(hm, ex, j, 16);
            float x1 = __shfl_sync(hm, ex, j + 1, 16);
            float x2 = __shfl_sync(hm, ex, j + 2, 16);
            float x3 = __shfl_sync(hm, ex, j + 3, 16);
            float4 h0 = __ldg(H4 + (long)s0 * 16 + l);
            float4 h1 = __ldg(H4 + (long)s1 * 16 + l);
            float4 h2 = __ldg(H4 + (long)s2 * 16 + l);
            float4 h3 = __ldg(H4 + (long)s3 * 16 + l);
            acc.x += x0 * h0.x; acc.y += x0 * h0.y; acc.z += x0 * h0.z; acc.w += x0 * h0.w;
            acc.x += x1 * h1.x; acc.y += x1 * h1.y; acc.z += x1 * h1.z; acc.w += x1 * h1.w;
            acc.x += x2 * h2.x; acc.y += x2 * h2.y; acc.z += x2 * h2.z; acc.w += x2 * h2.w;
            acc.x += x3 * h3.x; acc.y += x3 * h3.y; acc.z += x3 * h3.z; acc.w += x3 * h3.w;
        }
        for (; j < cnt; j++) {
            int   sj = __shfl_sync(hm, s, j, 16);
            float xj = __shfl_sync(hm, ex, j, 16);
            float4 hj = __ldg(H4 + (long)sj * 16 + l);
            acc.x += xj * hj.x; acc.y += xj * hj.y; acc.z += xj * hj.z; acc.w += xj * hj.w;
        }
    }
#pragma unroll
    for (int m = 8; m; m >>= 1) dsum += __shfl_xor_sync(hm, dsum, m, 16);

    const float inv = 1.0f / (dsum + exs);
    float4 bb = __ldg((const float4*)b + l);
    float4 r = make_float4(acc.x * inv + bb.x, acc.y * inv + bb.y,
                           acc.z * inv + bb.z, acc.w * inv + bb.w);

    if (mode == 1) {
        r.x = fmaxf(r.x, 0.f); r.y = fmaxf(r.y, 0.f);
        r.z = fmaxf(r.z, 0.f); r.w = fmaxf(r.w, 0.f);
        ((float4*)g_feat)[(long)node * 16 + l] = r;
    } else {
        // fused global mean pool
        __syncwarp(FULLM);
        r.x += __shfl_xor_sync(FULLM, r.x, 16);
        r.y += __shfl_xor_sync(FULLM, r.y, 16);
        r.z += __shfl_xor_sync(FULLM, r.z, 16);
        r.w += __shfl_xor_sync(FULLM, r.w, 16);
        if (lane < 16) {
            atomicAdd(&sred[4 * l + 0], r.x);
            atomicAdd(&sred[4 * l + 1], r.y);
            atomicAdd(&sred[4 * l + 2], r.z);
            atomicAdd(&sred[4 * l + 3], r.w);
        }
        __syncthreads();
        if (threadIdx.x < 64)
            atomicAdd(&out[threadIdx.x], sred[threadIdx.x] * (1.0f / N_NODES));
    }
}

// ---------------- launch ----------------
extern "C" void kernel_launch(void* const* d_in, const int* in_sizes, int n_in,
                              void* d_out, int out_size) {
    const float* x   = (const float*)d_in[0];
    const int*   ei  = (const int*)d_in[1];
    // d_in[2] = edge_attr (unused; GATConv edge_dim=None)
    const float* W1  = (const float*)d_in[3];
    const float* as1 = (const float*)d_in[4];
    const float* ad1 = (const float*)d_in[5];
    const float* b1  = (const float*)d_in[6];
    const float* W2  = (const float*)d_in[7];
    const float* as2 = (const float*)d_in[8];
    const float* ad2 = (const float*)d_in[9];
    const float* b2  = (const float*)d_in[10];
    float* out = (float*)d_out;

    // (0) layer-1 gemm + dst histogram (fused, complementary pipes)
    k_gemm<128, true><<<GB_GEMM + GB_HIST, 256>>>(x, W1, as1, ad1, ei, out);
    // (1) rowptr via single-kernel decoupled lookback scan
    k_scan<<<NB_SCAN, 1024>>>();
    // (2) adjacency fill + scratch reset for next call
    k_fill<<<3125, 512>>>(ei);
    // (3) layer-1 aggregation
    k_agg<<<3125, 512>>>(b1, out, 1);
    // (4) layer-2 gemm (+ zero out)
    k_gemm<64, false><<<GB_GEMM, 256>>>(nullptr, W2, as2, ad2, nullptr, out);
    // (5) layer-2 aggregation + fused global mean pool
    k_agg<<<3125, 512>>>(b2, out, 2);
}